// round 15
// baseline (speedup 1.0000x reference)
#include <cuda_runtime.h>
#include <cstdint>

// Problem constants
#define Bq 4
#define Pq 20000
#define NBq 9
#define WNq 17
#define CIq 64
#define COq 128
#define Tq 16          // points per CTA
#define Mq 64          // GEMM M rows per CTA = Bq*Tq
#define NTHREADS 256
#define SFP 72         // padded pitch for fuse tile (conflict-aware, 16B-aligned rows)

// Shared memory layout (in floats)
#define OFF_SX 0
#define SZ_SX (NBq*Mq*CIq)            // 36864  gathered neighbors [n][r][i]
#define OFF_SW (OFF_SX + SZ_SX)       // 36864
#define SZ_SW (CIq*COq)               // 8192   W slice, K-major [i][o]
#define OFF_SF (OFF_SW + SZ_SW)       // 45056
#define SZ_SF (CIq*SFP)               // 4608   fuse tile [k][r] (pitch 72)
#define OFF_WW (OFF_SF + SZ_SF)       // 49664
#define SZ_WW (Tq*NBq*WNq)            // 2448   masked point weights [t][n][m]
#define OFF_NID (OFF_WW + SZ_WW)      // 52112
#define SZ_NID (Tq*NBq)               // 144 ints
#define SMEM_FLOATS (OFF_NID + SZ_NID)
#define SMEM_BYTES (SMEM_FLOATS*4)    // 209024 bytes

// Pre-transposed weights: d_Wt[m][i][o] = weights[m][o][i]
__device__ float d_Wt[WNq*CIq*COq];

__global__ void lasm_transpose_w(const float* __restrict__ w) {
    int idx = blockIdx.x * 256 + threadIdx.x;
    if (idx < WNq * COq * CIq) {
        int m   = idx / (COq * CIq);
        int rem = idx - m * (COq * CIq);
        int o   = rem >> 6;     // / CIq
        int i   = rem & 63;     // % CIq
        d_Wt[m * (COq * CIq) + i * COq + o] = w[idx];
    }
}

__device__ __forceinline__ unsigned long long dup_f32x2(float x) {
    unsigned long long r;
    unsigned u = __float_as_uint(x);
    asm("mov.b64 %0, {%1, %1};" : "=l"(r) : "r"(u));
    return r;
}

__device__ __forceinline__ void fma_f32x2(unsigned long long& c,
                                          unsigned long long a,
                                          unsigned long long b) {
    asm("fma.rn.f32x2 %0, %1, %2, %0;" : "+l"(c) : "l"(a), "l"(b));
}

__device__ __forceinline__ float2 unpack_f32x2(unsigned long long v) {
    float2 r;
    r.x = __uint_as_float((unsigned)(v & 0xFFFFFFFFull));
    r.y = __uint_as_float((unsigned)(v >> 32));
    return r;
}

__device__ __forceinline__ float elu1(float x) {
    return x > 0.0f ? x : expm1f(x);
}

__global__ __launch_bounds__(NTHREADS, 1)
void lasm_main(const float* __restrict__ in_pc,    // [B][P][CI]
               const float* __restrict__ raw_w,    // [P][NB][WN]
               const float* __restrict__ bias,     // [P][CO]
               const int*   __restrict__ nids,     // [P][NB]
               float*       __restrict__ out)      // [B][P][CO]
{
    extern __shared__ float smem[];
    float* sX  = smem + OFF_SX;           // [NB][Mq][CI]
    float* sW  = smem + OFF_SW;           // [CI][CO]
    float* sF  = smem + OFF_SF;           // [CI][SFP]
    float* sWw = smem + OFF_WW;           // [T][NB][WN]
    int*   sNid = (int*)(smem + OFF_NID); // [T][NB]

    const int tid = threadIdx.x;
    const int p0  = blockIdx.x * Tq;

    // ---- load neighbor ids ----
    if (tid < Tq * NBq) sNid[tid] = nids[p0 * NBq + tid];
    __syncthreads();

    // ---- load masked point weights ----
    for (int idx = tid; idx < Tq * NBq * WNq; idx += NTHREADS) {
        int t   = idx / (NBq * WNq);
        int rem = idx - t * (NBq * WNq);
        int n   = rem / WNq;
        float v = raw_w[(size_t)(p0 + t) * (NBq * WNq) + rem];
        sWw[idx] = (sNid[t * NBq + n] < Pq) ? v : 0.0f;
    }

    // ---- gather neighbor features (float4 granularity) ----
    {
        float4* sX4 = (float4*)sX;
        const float4* in4 = (const float4*)in_pc;
        #pragma unroll
        for (int it = 0; it < (NBq * Mq * (CIq / 4)) / NTHREADS; ++it) {
            int idx = tid + it * NTHREADS;
            int i4 = idx & 15;
            int r  = (idx >> 4) & 63;
            int n  = idx >> 10;
            int t  = r & 15;
            int b  = r >> 4;
            int g  = sNid[t * NBq + n];
            float4 v = make_float4(0.f, 0.f, 0.f, 0.f);
            if (g < Pq) v = in4[((size_t)b * Pq + g) * (CIq / 4) + i4];
            sX4[idx] = v;
        }
    }

    // ---- accumulators: 4 rows x 4 f32x2-pairs (= 4x8 fp32 tile) ----
    unsigned long long acc[4][4];
    #pragma unroll
    for (int a = 0; a < 4; ++a)
        #pragma unroll
        for (int c = 0; c < 4; ++c) acc[a][c] = 0ULL;

    const int r0 = (tid & 15) * 4;    // M-tile base row (0..60)
    const int n0 = (tid >> 4) * 8;    // N-tile base col (0..120)

    __syncthreads();

    // ---- main loop over WN slices ----
    for (int m = 0; m < WNq; ++m) {
        // stage W(m) into smem, K-major (coalesced copy, pre-transposed in global)
        {
            const float4* wsrc = (const float4*)(d_Wt + m * (CIq * COq));
            float4* wdst = (float4*)sW;
            #pragma unroll
            for (int j = 0; j < (CIq * COq / 4) / NTHREADS; ++j)
                wdst[tid + j * NTHREADS] = wsrc[tid + j * NTHREADS];
        }

        // compute fuse(m): sF[i][r] = sum_n sWw[t][n][m] * sX[n][r][i]
        {
            const int ip = tid & 31;        // i-pair index, i = 2*ip
            const int rb = (tid >> 5) * 8;  // 8 rows per thread
            const float2* sX2 = (const float2*)sX;
            #pragma unroll
            for (int j = 0; j < 8; ++j) {
                int r = rb + j;
                int t = r & 15;
                float f0 = 0.f, f1 = 0.f;
                #pragma unroll
                for (int n = 0; n < NBq; ++n) {
                    float w  = sWw[(t * NBq + n) * WNq + m];
                    float2 x = sX2[(n * Mq + r) * (CIq / 2) + ip];
                    f0 = fmaf(w, x.x, f0);
                    f1 = fmaf(w, x.y, f1);
                }
                sF[(2 * ip)     * SFP + r] = f0;
                sF[(2 * ip + 1) * SFP + r] = f1;
            }
        }
        __syncthreads();

        // GEMM: acc[r0..r0+3][n0..n0+7] += sF^T(64xK... ) * sW
        #pragma unroll 8
        for (int k = 0; k < CIq; ++k) {
            float4 a4 = *(const float4*)&sF[k * SFP + r0];
            ulonglong2 b0 = *(const ulonglong2*)&sW[k * COq + n0];
            ulonglong2 b1 = *(const ulonglong2*)&sW[k * COq + n0 + 4];
            unsigned long long aa;
            aa = dup_f32x2(a4.x);
            fma_f32x2(acc[0][0], aa, b0.x); fma_f32x2(acc[0][1], aa, b0.y);
            fma_f32x2(acc[0][2], aa, b1.x); fma_f32x2(acc[0][3], aa, b1.y);
            aa = dup_f32x2(a4.y);
            fma_f32x2(acc[1][0], aa, b0.x); fma_f32x2(acc[1][1], aa, b0.y);
            fma_f32x2(acc[1][2], aa, b1.x); fma_f32x2(acc[1][3], aa, b1.y);
            aa = dup_f32x2(a4.z);
            fma_f32x2(acc[2][0], aa, b0.x); fma_f32x2(acc[2][1], aa, b0.y);
            fma_f32x2(acc[2][2], aa, b1.x); fma_f32x2(acc[2][3], aa, b1.y);
            aa = dup_f32x2(a4.w);
            fma_f32x2(acc[3][0], aa, b0.x); fma_f32x2(acc[3][1], aa, b0.y);
            fma_f32x2(acc[3][2], aa, b1.x); fma_f32x2(acc[3][3], aa, b1.y);
        }
        __syncthreads();
    }

    // ---- epilogue: bias + ELU + store ----
    #pragma unroll
    for (int ii = 0; ii < 4; ++ii) {
        int r = r0 + ii;
        int b = r >> 4;
        int t = r & 15;
        int p = p0 + t;
        const float* bp = bias + (size_t)p * COq;
        float*       op = out  + ((size_t)b * Pq + p) * COq;
        #pragma unroll
        for (int g = 0; g < 2; ++g) {
            int n = n0 + 4 * g;
            float2 c0 = unpack_f32x2(acc[ii][2 * g]);
            float2 c1 = unpack_f32x2(acc[ii][2 * g + 1]);
            float4 bv = *(const float4*)&bp[n];
            float4 ov;
            ov.x = elu1(c0.x + bv.x);
            ov.y = elu1(c0.y + bv.y);
            ov.z = elu1(c1.x + bv.z);
            ov.w = elu1(c1.y + bv.w);
            *(float4*)&op[n] = ov;
        }
    }
}

extern "C" void kernel_launch(void* const* d_in, const int* in_sizes, int n_in,
                              void* d_out, int out_size) {
    const float* in_pc   = (const float*)d_in[0];  // (B,P,CI)
    const float* raw_w   = (const float*)d_in[1];  // (P,NB,WN)
    const float* weights = (const float*)d_in[2];  // (WN, CO*CI)
    const float* bias    = (const float*)d_in[3];  // (P,CO)
    const int*   nids    = (const int*)d_in[4];    // (P,NB)
    float*       out     = (float*)d_out;          // (B,P,CO)

    cudaFuncSetAttribute(lasm_main,
                         cudaFuncAttributeMaxDynamicSharedMemorySize,
                         SMEM_BYTES);

    // 1) pre-transpose W to K-major once per launch (cheap: 0.56 MB)
    int nW = WNq * COq * CIq;
    lasm_transpose_w<<<(nW + 255) / 256, 256>>>(weights);

    // 2) fused gather + fuse + GEMM + bias + ELU
    lasm_main<<<Pq / Tq, NTHREADS, SMEM_BYTES>>>(in_pc, raw_w, bias, nids, out);
}

// round 16
// speedup vs baseline: 1.0015x; 1.0015x over previous
#include <cuda_runtime.h>
#include <cstdint>

// Problem constants
#define Bq 4
#define Pq 20000
#define NBq 9
#define WNq 17
#define CIq 64
#define COq 128
#define Tq 16          // points per CTA
#define Mq 64          // GEMM M rows per CTA = Bq*Tq
#define NTHREADS 256
#define SFP 72         // padded pitch for fuse tile (conflict-aware, 16B-aligned rows)

// Shared memory layout (in floats)
#define OFF_SX 0
#define SZ_SX (NBq*Mq*CIq)            // 36864  gathered neighbors [n][r][i]
#define OFF_SW (OFF_SX + SZ_SX)       // 36864
#define SZ_SW (CIq*COq)               // 8192   W slice, K-major [i][o]
#define OFF_SF (OFF_SW + SZ_SW)       // 45056
#define SZ_SF (CIq*SFP)               // 4608   fuse tile [k][r] (pitch 72)
#define OFF_WW (OFF_SF + SZ_SF)       // 49664
#define SZ_WW (Tq*NBq*WNq)            // 2448   masked point weights [t][n][m]
#define OFF_NID (OFF_WW + SZ_WW)      // 52112
#define SZ_NID (Tq*NBq)               // 144 ints
#define SMEM_FLOATS (OFF_NID + SZ_NID)
#define SMEM_BYTES (SMEM_FLOATS*4)    // 209024 bytes

// Pre-transposed weights: d_Wt[m][i][o] = weights[m][o][i]
__device__ float d_Wt[WNq*CIq*COq];

__global__ void lasm_transpose_w(const float* __restrict__ w) {
    int idx = blockIdx.x * 256 + threadIdx.x;
    if (idx < WNq * COq * CIq) {
        int m   = idx / (COq * CIq);
        int rem = idx - m * (COq * CIq);
        int o   = rem >> 6;     // / CIq
        int i   = rem & 63;     // % CIq
        d_Wt[m * (COq * CIq) + i * COq + o] = w[idx];
    }
}

__device__ __forceinline__ unsigned long long dup_f32x2(float x) {
    unsigned long long r;
    unsigned u = __float_as_uint(x);
    asm("mov.b64 %0, {%1, %1};" : "=l"(r) : "r"(u));
    return r;
}

__device__ __forceinline__ void fma_f32x2(unsigned long long& c,
                                          unsigned long long a,
                                          unsigned long long b) {
    asm("fma.rn.f32x2 %0, %1, %2, %0;" : "+l"(c) : "l"(a), "l"(b));
}

__device__ __forceinline__ float2 unpack_f32x2(unsigned long long v) {
    float2 r;
    r.x = __uint_as_float((unsigned)(v & 0xFFFFFFFFull));
    r.y = __uint_as_float((unsigned)(v >> 32));
    return r;
}

__device__ __forceinline__ float elu1(float x) {
    return x > 0.0f ? x : expm1f(x);
}

__global__ __launch_bounds__(NTHREADS, 1)
void lasm_main(const float* __restrict__ in_pc,    // [B][P][CI]
               const float* __restrict__ raw_w,    // [P][NB][WN]
               const float* __restrict__ bias,     // [P][CO]
               const int*   __restrict__ nids,     // [P][NB]
               float*       __restrict__ out)      // [B][P][CO]
{
    extern __shared__ float smem[];
    float* sX  = smem + OFF_SX;           // [NB][Mq][CI]
    float* sW  = smem + OFF_SW;           // [CI][CO]
    float* sF  = smem + OFF_SF;           // [CI][SFP]
    float* sWw = smem + OFF_WW;           // [T][NB][WN]
    int*   sNid = (int*)(smem + OFF_NID); // [T][NB]

    const int tid = threadIdx.x;
    const int p0  = blockIdx.x * Tq;

    // ---- load neighbor ids ----
    if (tid < Tq * NBq) sNid[tid] = nids[p0 * NBq + tid];
    __syncthreads();

    // ---- load masked point weights ----
    for (int idx = tid; idx < Tq * NBq * WNq; idx += NTHREADS) {
        int t   = idx / (NBq * WNq);
        int rem = idx - t * (NBq * WNq);
        int n   = rem / WNq;
        float v = raw_w[(size_t)(p0 + t) * (NBq * WNq) + rem];
        sWw[idx] = (sNid[t * NBq + n] < Pq) ? v : 0.0f;
    }

    // ---- gather neighbor features (float4 granularity) ----
    {
        float4* sX4 = (float4*)sX;
        const float4* in4 = (const float4*)in_pc;
        #pragma unroll
        for (int it = 0; it < (NBq * Mq * (CIq / 4)) / NTHREADS; ++it) {
            int idx = tid + it * NTHREADS;
            int i4 = idx & 15;
            int r  = (idx >> 4) & 63;
            int n  = idx >> 10;
            int t  = r & 15;
            int b  = r >> 4;
            int g  = sNid[t * NBq + n];
            float4 v = make_float4(0.f, 0.f, 0.f, 0.f);
            if (g < Pq) v = in4[((size_t)b * Pq + g) * (CIq / 4) + i4];
            sX4[idx] = v;
        }
    }

    // ---- accumulators: 4 rows x 4 f32x2-pairs (= 4x8 fp32 tile) ----
    unsigned long long acc[4][4];
    #pragma unroll
    for (int a = 0; a < 4; ++a)
        #pragma unroll
        for (int c = 0; c < 4; ++c) acc[a][c] = 0ULL;

    const int r0 = (tid & 15) * 4;    // M-tile base row (0..60)
    const int n0 = (tid >> 4) * 8;    // N-tile base col (0..120)

    __syncthreads();

    // ---- main loop over WN slices ----
    for (int m = 0; m < WNq; ++m) {
        // stage W(m) into smem, K-major (coalesced copy, pre-transposed in global)
        {
            const float4* wsrc = (const float4*)(d_Wt + m * (CIq * COq));
            float4* wdst = (float4*)sW;
            #pragma unroll
            for (int j = 0; j < (CIq * COq / 4) / NTHREADS; ++j)
                wdst[tid + j * NTHREADS] = wsrc[tid + j * NTHREADS];
        }

        // compute fuse(m): sF[i][r] = sum_n sWw[t][n][m] * sX[n][r][i]
        {
            const int ip = tid & 31;        // i-pair index, i = 2*ip
            const int rb = (tid >> 5) * 8;  // 8 rows per thread
            const float2* sX2 = (const float2*)sX;
            #pragma unroll
            for (int j = 0; j < 8; ++j) {
                int r = rb + j;
                int t = r & 15;
                float f0 = 0.f, f1 = 0.f;
                #pragma unroll
                for (int n = 0; n < NBq; ++n) {
                    float w  = sWw[(t * NBq + n) * WNq + m];
                    float2 x = sX2[(n * Mq + r) * (CIq / 2) + ip];
                    f0 = fmaf(w, x.x, f0);
                    f1 = fmaf(w, x.y, f1);
                }
                sF[(2 * ip)     * SFP + r] = f0;
                sF[(2 * ip + 1) * SFP + r] = f1;
            }
        }
        __syncthreads();

        // GEMM: acc[r0..r0+3][n0..n0+7] += sF^T(64xK... ) * sW
        #pragma unroll 8
        for (int k = 0; k < CIq; ++k) {
            float4 a4 = *(const float4*)&sF[k * SFP + r0];
            ulonglong2 b0 = *(const ulonglong2*)&sW[k * COq + n0];
            ulonglong2 b1 = *(const ulonglong2*)&sW[k * COq + n0 + 4];
            unsigned long long aa;
            aa = dup_f32x2(a4.x);
            fma_f32x2(acc[0][0], aa, b0.x); fma_f32x2(acc[0][1], aa, b0.y);
            fma_f32x2(acc[0][2], aa, b1.x); fma_f32x2(acc[0][3], aa, b1.y);
            aa = dup_f32x2(a4.y);
            fma_f32x2(acc[1][0], aa, b0.x); fma_f32x2(acc[1][1], aa, b0.y);
            fma_f32x2(acc[1][2], aa, b1.x); fma_f32x2(acc[1][3], aa, b1.y);
            aa = dup_f32x2(a4.z);
            fma_f32x2(acc[2][0], aa, b0.x); fma_f32x2(acc[2][1], aa, b0.y);
            fma_f32x2(acc[2][2], aa, b1.x); fma_f32x2(acc[2][3], aa, b1.y);
            aa = dup_f32x2(a4.w);
            fma_f32x2(acc[3][0], aa, b0.x); fma_f32x2(acc[3][1], aa, b0.y);
            fma_f32x2(acc[3][2], aa, b1.x); fma_f32x2(acc[3][3], aa, b1.y);
        }
        __syncthreads();
    }

    // ---- epilogue: bias + ELU + store ----
    #pragma unroll
    for (int ii = 0; ii < 4; ++ii) {
        int r = r0 + ii;
        int b = r >> 4;
        int t = r & 15;
        int p = p0 + t;
        const float* bp = bias + (size_t)p * COq;
        float*       op = out  + ((size_t)b * Pq + p) * COq;
        #pragma unroll
        for (int g = 0; g < 2; ++g) {
            int n = n0 + 4 * g;
            float2 c0 = unpack_f32x2(acc[ii][2 * g]);
            float2 c1 = unpack_f32x2(acc[ii][2 * g + 1]);
            float4 bv = *(const float4*)&bp[n];
            float4 ov;
            ov.x = elu1(c0.x + bv.x);
            ov.y = elu1(c0.y + bv.y);
            ov.z = elu1(c1.x + bv.z);
            ov.w = elu1(c1.y + bv.w);
            *(float4*)&op[n] = ov;
        }
    }
}

extern "C" void kernel_launch(void* const* d_in, const int* in_sizes, int n_in,
                              void* d_out, int out_size) {
    const float* in_pc   = (const float*)d_in[0];  // (B,P,CI)
    const float* raw_w   = (const float*)d_in[1];  // (P,NB,WN)
    const float* weights = (const float*)d_in[2];  // (WN, CO*CI)
    const float* bias    = (const float*)d_in[3];  // (P,CO)
    const int*   nids    = (const int*)d_in[4];    // (P,NB)
    float*       out     = (float*)d_out;          // (B,P,CO)

    cudaFuncSetAttribute(lasm_main,
                         cudaFuncAttributeMaxDynamicSharedMemorySize,
                         SMEM_BYTES);

    // 1) pre-transpose W to K-major once per launch (cheap: 0.56 MB)
    int nW = WNq * COq * CIq;
    lasm_transpose_w<<<(nW + 255) / 256, 256>>>(weights);

    // 2) fused gather + fuse + GEMM + bias + ELU
    lasm_main<<<Pq / Tq, NTHREADS, SMEM_BYTES>>>(in_pc, raw_w, bias, nids, out);
}